// round 3
// baseline (speedup 1.0000x reference)
#include <cuda_runtime.h>
#include <math.h>

// Problem constants
#define BB      2
#define CIN_    64
#define LSEQ    4096            // H*W
#define NTOK    (BB*LSEQ)       // 8192
#define DM      64              // d_model
#define DI      128             // d_inner
#define DS      16              // d_state
#define DR      32              // dt_rank

// ---------------- device scratch (static, allocation-free) ----------------
__device__ float g_rgb  [NTOK*DM];
__device__ float g_dte  [NTOK*DM];
__device__ float g_O0   [NTOK*DM];
__device__ float g_O1   [NTOK*DM];
__device__ float g_h    [NTOK*DI*DS];   // 64 MB
__device__ float g_A    [DI*DS];

// ---------------- A = -exp(A_log) ----------------
__global__ void k_prep_A(const float* __restrict__ A_log) {
    int i = blockIdx.x * blockDim.x + threadIdx.x;
    if (i < DI*DS) g_A[i] = -expf(A_log[i]);
}

// ---------------- 1x1 conv, channel-major in -> token-major out ----------------
__global__ __launch_bounds__(256) void k_conv_in(const float* __restrict__ in,
                                                 const float* __restrict__ w,
                                                 const float* __restrict__ bias,
                                                 float* __restrict__ out) {
    __shared__ float s_in[CIN_][65];
    __shared__ float s_w [DM][65];
    int bx  = blockIdx.x;
    int b   = bx >> 6;
    int l0  = (bx & 63) << 6;
    int tid = threadIdx.x;
    for (int i = tid; i < CIN_*64; i += 256) {
        int c = i >> 6, ll = i & 63;
        s_in[c][ll] = in[(b*CIN_ + c)*LSEQ + l0 + ll];
    }
    for (int i = tid; i < DM*CIN_; i += 256) {
        int o = i >> 6, c = i & 63;
        s_w[o][c] = w[i];
    }
    __syncthreads();
    int o  = tid & 63;
    int lg = tid >> 6;
    for (int li = 0; li < 16; ++li) {
        int ll = lg*16 + li;
        float acc = bias[o];
        #pragma unroll 16
        for (int c = 0; c < CIN_; ++c) acc += s_w[o][c] * s_in[c][ll];
        out[(b*LSEQ + l0 + ll)*DM + o] = acc;
    }
}

// ---------------- final 1x1 conv, token-major in -> channel-major out ----------------
__global__ __launch_bounds__(256) void k_conv3(const float* __restrict__ in6,
                                               const float* __restrict__ w,
                                               const float* __restrict__ bias,
                                               float* __restrict__ out) {
    __shared__ float s_in[64][65];
    __shared__ float s_w [CIN_][65];
    int bx  = blockIdx.x;
    int b   = bx >> 6;
    int l0  = (bx & 63) << 6;
    int tid = threadIdx.x;
    for (int i = tid; i < 64*DM; i += 256) {
        int t = i >> 6, c = i & 63;
        s_in[t][c] = in6[(b*LSEQ + l0 + t)*DM + c];
    }
    for (int i = tid; i < CIN_*DM; i += 256) {
        int o = i >> 6, c = i & 63;
        s_w[o][c] = w[i];
    }
    __syncthreads();
    int t  = tid & 63;
    int og = tid >> 6;
    for (int oi = 0; oi < 16; ++oi) {
        int o = og*16 + oi;
        float acc = bias[o];
        #pragma unroll 16
        for (int c = 0; c < DM; ++c) acc += s_w[o][c] * s_in[t][c];
        out[(b*CIN_ + o)*LSEQ + l0 + t] = acc;
    }
}

// ---------------- fused per-block kernel ----------------
// CTA = 32 own tokens + 2-token halo (for conv1d), 256 threads.
// Halo rows of the residual stream are re-normalized + re-projected (in_proj has
// no bias, so zeroed out-of-range rows give exactly the reference zero padding).
//
// dynamic smem layout (floats):
#define OFF_X     0                       // 34 x 68   (residual stream -> normalized x)
#define OFF_XCALL (OFF_X    + 34*68)      // 34 x 132  (xc_pre for conv; later aliased as ym)
#define OFF_Z     (OFF_XCALL+ 34*132)     // 32 x 129
#define OFF_XC    (OFF_Z    + 32*129)     // 32 x 132  (post conv+silu)
#define OFF_DBC   (OFF_XC   + 32*132)     // 32 x 65   (delta_in | B | C)
#define OFF_DL    (OFF_DBC  + 32*65)      // 32 x 129  (softplus delta)
#define OFF_A     (OFF_DL   + 32*129)     // 128 x 17
#define OFF_RMS   (OFF_A    + 128*17)     // 40
#define SMF_TOT   (OFF_RMS  + 40)

__global__ __launch_bounds__(256, 2) void k_block(
        const float* __restrict__ base, const float* __restrict__ prev,
        const float* __restrict__ norm_w, const float* __restrict__ in_w,
        const float* __restrict__ cw,   const float* __restrict__ cb,
        const float* __restrict__ xp_w,
        const float* __restrict__ dt_w, const float* __restrict__ dt_b,
        const float* __restrict__ Dp,
        const float* __restrict__ out_w,
        const float* __restrict__ h_in, float* __restrict__ h_out,
        float* __restrict__ out_cur) {
    extern __shared__ float sm[];
    float* s_x    = sm + OFF_X;
    float* s_xcal = sm + OFF_XCALL;
    float* s_ym   = sm + OFF_XCALL;   // alias: xc_pre dead after conv
    float* s_z    = sm + OFF_Z;
    float* s_xc   = sm + OFF_XC;
    float* s_dbc  = sm + OFF_DBC;
    float* s_dl   = sm + OFF_DL;
    float* s_A    = sm + OFF_A;
    float* s_rms  = sm + OFF_RMS;

    int tok0 = blockIdx.x * 32;
    int tid  = threadIdx.x;
    int l0   = tok0 & (LSEQ - 1);     // CTA stays inside one batch (4096 % 32 == 0)

    for (int i = tid; i < DI*DS; i += 256) { int d = i >> 4, s = i & 15; s_A[d*17 + s] = g_A[i]; }

    // ---- stage A: load residual stream for 34 rows (ht: 0=l0-1 .. 33=l0+32) ----
    for (int i = tid; i < 34*64; i += 256) {
        int ht = i >> 6, c = i & 63;
        int l  = l0 - 1 + ht;
        float v = 0.f;
        if (l >= 0 && l < LSEQ) {
            int gt = (tok0 - l0) + l;     // batch-global token
            v = base[gt*DM + c];
            if (prev) v += prev[gt*DM + c];
        }
        s_x[ht*68 + c] = v;
    }
    __syncthreads();
    // rmsnorm: 4 threads per row. Use 5 FULL warps (tid < 160) so every lane of
    // every participating warp is active for the full-mask shuffles; threads
    // beyond row 33 clamp to row 33 and redundantly write the same value.
    if (tid < 160) {
        int ht = tid >> 2; if (ht > 33) ht = 33;
        int j = tid & 3;
        float s = 0.f;
        #pragma unroll
        for (int k = 0; k < 16; ++k) { float v = s_x[ht*68 + j + 4*k]; s += v*v; }
        s += __shfl_xor_sync(0xFFFFFFFFu, s, 2, 4);
        s += __shfl_xor_sync(0xFFFFFFFFu, s, 1, 4);
        if (j == 0) s_rms[ht] = rsqrtf(s * (1.0f/64.0f) + 1e-5f);
    }
    __syncthreads();
    for (int i = tid; i < 34*64; i += 256) {
        int ht = i >> 6, c = i & 63;
        s_x[ht*68 + c] *= s_rms[ht] * norm_w[c];
    }
    __syncthreads();

    int lane = tid & 31, wj = tid >> 5;

    // ---- stage B: in_proj ----
    // main: lane = own token (row lane+1), warp wj covers o in [wj*32, wj*32+32)
    {
        const float4* xrow = (const float4*)(s_x + (lane + 1)*68);
        #pragma unroll 2
        for (int oi = 0; oi < 32; oi += 4) {
            int o = wj*32 + oi;
            const float4* w0 = (const float4*)(in_w + (o+0)*64);
            const float4* w1 = (const float4*)(in_w + (o+1)*64);
            const float4* w2 = (const float4*)(in_w + (o+2)*64);
            const float4* w3 = (const float4*)(in_w + (o+3)*64);
            float a0 = 0.f, a1 = 0.f, a2 = 0.f, a3 = 0.f;
            #pragma unroll
            for (int k = 0; k < 16; ++k) {
                float4 xv = xrow[k];
                float4 v0 = __ldg(&w0[k]), v1 = __ldg(&w1[k]);
                float4 v2 = __ldg(&w2[k]), v3 = __ldg(&w3[k]);
                a0 += v0.x*xv.x + v0.y*xv.y + v0.z*xv.z + v0.w*xv.w;
                a1 += v1.x*xv.x + v1.y*xv.y + v1.z*xv.z + v1.w*xv.w;
                a2 += v2.x*xv.x + v2.y*xv.y + v2.z*xv.z + v2.w*xv.w;
                a3 += v3.x*xv.x + v3.y*xv.y + v3.z*xv.z + v3.w*xv.w;
            }
            if (o < DI) {
                float* dst = s_xcal + (lane + 1)*132 + o;
                dst[0] = a0; dst[1] = a1; dst[2] = a2; dst[3] = a3;
            } else {
                float* dst = s_z + lane*129 + (o - DI);
                dst[0] = a0; dst[1] = a1; dst[2] = a2; dst[3] = a3;
            }
        }
    }
    // halo: one thread per (halo row, o<128) dot product
    {
        int o  = tid & 127;
        int ht = (tid >> 7) ? 33 : 0;
        const float4* wr = (const float4*)(in_w + o*64);
        const float4* xr = (const float4*)(s_x + ht*68);
        float a = 0.f;
        #pragma unroll
        for (int k = 0; k < 16; ++k) {
            float4 wv = __ldg(&wr[k]); float4 xv = xr[k];
            a += wv.x*xv.x + wv.y*xv.y + wv.z*xv.z + wv.w*xv.w;
        }
        s_xcal[ht*132 + o] = a;
    }
    __syncthreads();

    // ---- stage C: depthwise conv (taps rows t, t+1, t+2) + SiLU ----
    for (int i = tid; i < 32*DI; i += 256) {
        int t = i >> 7, d = i & 127;
        float v = cb[d]
                + cw[d*3 + 0] * s_xcal[(t+0)*132 + d]
                + cw[d*3 + 1] * s_xcal[(t+1)*132 + d]
                + cw[d*3 + 2] * s_xcal[(t+2)*132 + d];
        v = v / (1.0f + __expf(-v));
        s_xc[t*132 + d] = v;
    }
    __syncthreads();

    // ---- stage D: x_proj (64 outputs), warp wj handles 8 ----
    {
        const float4* xrow = (const float4*)(s_xc + lane*132);
        float a[8];
        #pragma unroll
        for (int oi = 0; oi < 8; ++oi) a[oi] = 0.f;
        #pragma unroll 8
        for (int c4 = 0; c4 < 32; ++c4) {
            float4 xv = xrow[c4];
            #pragma unroll
            for (int oi = 0; oi < 8; ++oi) {
                float4 wv = __ldg((const float4*)(xp_w + (wj*8 + oi)*DI + 4*c4));
                a[oi] += wv.x*xv.x + wv.y*xv.y + wv.z*xv.z + wv.w*xv.w;
            }
        }
        #pragma unroll
        for (int oi = 0; oi < 8; ++oi) s_dbc[lane*65 + wj*8 + oi] = a[oi];
    }
    __syncthreads();

    // ---- stage E: dt_proj + softplus ----
    {
        float din[DR];
        #pragma unroll
        for (int r = 0; r < DR; ++r) din[r] = s_dbc[lane*65 + r];
        #pragma unroll 2
        for (int oi = 0; oi < 16; ++oi) {
            int o = wj*16 + oi;
            const float4* wr = (const float4*)(dt_w + o*DR);
            float a = dt_b[o];
            #pragma unroll
            for (int r4 = 0; r4 < 8; ++r4) {
                float4 wv = __ldg(&wr[r4]);
                a += wv.x*din[4*r4] + wv.y*din[4*r4+1] + wv.z*din[4*r4+2] + wv.w*din[4*r4+3];
            }
            float sp = fmaxf(a, 0.f) + log1pf(__expf(-fabsf(a)));
            s_dl[lane*129 + o] = sp;
        }
    }
    __syncthreads();

    // ---- stage F: SSM update + y + gating ----
    for (int i = tid; i < 32*DI; i += 256) {
        int t = i >> 7, d = i & 127;
        float dl  = s_dl[t*129 + d];
        float xcv = s_xc[t*132 + d];
        float dx  = dl * xcv;
        size_t hbase = ((size_t)(tok0 + t)*DI + d) * DS;
        float h[DS];
        if (h_in) {
            #pragma unroll
            for (int q = 0; q < 4; ++q) {
                float4 hv = *((const float4*)(h_in + hbase) + q);
                h[4*q] = hv.x; h[4*q+1] = hv.y; h[4*q+2] = hv.z; h[4*q+3] = hv.w;
            }
        } else {
            #pragma unroll
            for (int s = 0; s < DS; ++s) h[s] = 0.f;
        }
        float y = 0.f;
        #pragma unroll
        for (int s = 0; s < DS; ++s) {
            float dA = __expf(dl * s_A[d*17 + s]);
            float hn = dA * h[s] + dx * s_dbc[t*65 + 32 + s];
            h[s] = hn;
            y += hn * s_dbc[t*65 + 48 + s];
        }
        #pragma unroll
        for (int q = 0; q < 4; ++q)
            *((float4*)(h_out + hbase) + q) = make_float4(h[4*q], h[4*q+1], h[4*q+2], h[4*q+3]);
        y += __ldg(&Dp[d]) * xcv;
        float z  = s_z[t*129 + d];
        float sz = z / (1.0f + __expf(-z));
        s_ym[t*132 + d] = y * sz;   // overwrites xc_pre rows (dead)
    }
    __syncthreads();

    // ---- stage G: out_proj + residual(x_norm), staged then coalesced store ----
    {
        const float4* yrow = (const float4*)(s_ym + lane*132);
        float a[8];
        #pragma unroll
        for (int oi = 0; oi < 8; ++oi) a[oi] = 0.f;
        #pragma unroll 8
        for (int c4 = 0; c4 < 32; ++c4) {
            float4 yv = yrow[c4];
            #pragma unroll
            for (int oi = 0; oi < 8; ++oi) {
                float4 wv = __ldg((const float4*)(out_w + (wj*8 + oi)*DI + 4*c4));
                a[oi] += wv.x*yv.x + wv.y*yv.y + wv.z*yv.z + wv.w*yv.w;
            }
        }
        __syncthreads();   // s_dbc about to be reused
        #pragma unroll
        for (int oi = 0; oi < 8; ++oi) {
            int o = wj*8 + oi;
            s_dbc[lane*65 + o] = a[oi] + s_x[(lane + 1)*68 + o];
        }
    }
    __syncthreads();
    for (int i = tid; i < 32*64; i += 256) {
        int t = i >> 6, o = i & 63;
        out_cur[(tok0 + t)*DM + o] = s_dbc[t*65 + o];
    }
}

// ---------------- host launch ----------------
extern "C" void kernel_launch(void* const* d_in, const int* in_sizes, int n_in,
                              void* d_out, int out_size) {
    const float* rgb    = (const float*)d_in[0];
    const float* dte    = (const float*)d_in[1];
    const float* c1w    = (const float*)d_in[2];
    const float* c1b    = (const float*)d_in[3];
    const float* c2w    = (const float*)d_in[4];
    const float* c2b    = (const float*)d_in[5];
    const float* c3w    = (const float*)d_in[6];
    const float* c3b    = (const float*)d_in[7];
    const float* normw  = (const float*)d_in[8];
    const float* inw    = (const float*)d_in[9];
    const float* convw  = (const float*)d_in[10];
    const float* convb  = (const float*)d_in[11];
    const float* xpw    = (const float*)d_in[12];
    const float* dtw    = (const float*)d_in[13];
    const float* dtb    = (const float*)d_in[14];
    const float* A_log  = (const float*)d_in[15];
    const float* Dpp    = (const float*)d_in[16];
    const float* outw   = (const float*)d_in[17];
    float* out = (float*)d_out;

    float *p_rgb, *p_dte, *p_O0, *p_O1, *p_h;
    cudaGetSymbolAddress((void**)&p_rgb, g_rgb);
    cudaGetSymbolAddress((void**)&p_dte, g_dte);
    cudaGetSymbolAddress((void**)&p_O0,  g_O0);
    cudaGetSymbolAddress((void**)&p_O1,  g_O1);
    cudaGetSymbolAddress((void**)&p_h,   g_h);

    const int smemB = SMF_TOT * (int)sizeof(float);
    cudaFuncSetAttribute(k_block, cudaFuncAttributeMaxDynamicSharedMemorySize, smemB);

    const int conv_elems = BB*CIN_*LSEQ;                 // 524288
    const int h_elems    = NTOK*DI*DS;                   // 16777216
    float* h_final = (out_size >= conv_elems + h_elems) ? (out + conv_elems) : p_h;

    k_prep_A<<<(DI*DS + 255)/256, 256>>>(A_log);
    k_conv_in<<<BB*LSEQ/64, 256>>>(rgb, c1w, c1b, p_rgb);
    k_conv_in<<<BB*LSEQ/64, 256>>>(dte, c2w, c2b, p_dte);

    const float* bases[6] = { p_rgb, p_dte, p_rgb, p_dte, p_rgb, p_dte };
    float* outs[2] = { p_O0, p_O1 };
    const float* prev = nullptr;
    for (int k = 0; k < 6; ++k) {
        const float* h_in = (k == 0) ? nullptr : p_h;
        float* h_o        = (k == 5) ? h_final : p_h;
        k_block<<<NTOK/32, 256, smemB>>>(bases[k], prev, normw, inw,
                                         convw, convb, xpw, dtw, dtb, Dpp, outw,
                                         h_in, h_o, outs[k & 1]);
        prev = outs[k & 1];
    }
    k_conv3<<<BB*LSEQ/64, 256>>>(prev, c3w, c3b, out);
}

// round 5
// speedup vs baseline: 1.2480x; 1.2480x over previous
#include <cuda_runtime.h>
#include <math.h>

// Problem constants
#define BB      2
#define CIN_    64
#define LSEQ    4096            // H*W
#define NTOK    (BB*LSEQ)       // 8192
#define DM      64              // d_model
#define DI      128             // d_inner
#define DS      16              // d_state
#define DR      32              // dt_rank

// ---------------- device scratch (static, allocation-free) ----------------
__device__ float g_rgb  [NTOK*DM];
__device__ float g_dte  [NTOK*DM];
__device__ float g_xn   [NTOK*DM];
__device__ float g_xcpre[NTOK*DI];
__device__ float g_z    [NTOK*DI];
__device__ float g_O0   [NTOK*DM];
__device__ float g_O1   [NTOK*DM];
__device__ float g_h    [NTOK*DI*DS];   // 64 MB
__device__ float g_A    [DI*DS];

// ---------------- A = -exp(A_log) ----------------
__global__ void k_prep_A(const float* __restrict__ A_log) {
    int i = blockIdx.x * blockDim.x + threadIdx.x;
    if (i < DI*DS) g_A[i] = -expf(A_log[i]);
}

// ---------------- 1x1 conv, channel-major in -> token-major out (R1, proven) ----------------
__global__ __launch_bounds__(256) void k_conv_in(const float* __restrict__ in,
                                                 const float* __restrict__ w,
                                                 const float* __restrict__ bias,
                                                 float* __restrict__ out) {
    __shared__ float s_in[CIN_][65];
    __shared__ float s_w [DM][65];
    int bx  = blockIdx.x;
    int b   = bx >> 6;
    int l0  = (bx & 63) << 6;
    int tid = threadIdx.x;
    for (int i = tid; i < CIN_*64; i += 256) {
        int c = i >> 6, ll = i & 63;
        s_in[c][ll] = in[(b*CIN_ + c)*LSEQ + l0 + ll];
    }
    for (int i = tid; i < DM*CIN_; i += 256) {
        int o = i >> 6, c = i & 63;
        s_w[o][c] = w[i];
    }
    __syncthreads();
    int o  = tid & 63;
    int lg = tid >> 6;
    for (int li = 0; li < 16; ++li) {
        int ll = lg*16 + li;
        float acc = bias[o];
        #pragma unroll 16
        for (int c = 0; c < CIN_; ++c) acc += s_w[o][c] * s_in[c][ll];
        out[(b*LSEQ + l0 + ll)*DM + o] = acc;
    }
}

// ---------------- final 1x1 conv, token-major in -> channel-major out (R1, proven) ----------------
__global__ __launch_bounds__(256) void k_conv3(const float* __restrict__ in6,
                                               const float* __restrict__ w,
                                               const float* __restrict__ bias,
                                               float* __restrict__ out) {
    __shared__ float s_in[64][65];
    __shared__ float s_w [CIN_][65];
    int bx  = blockIdx.x;
    int b   = bx >> 6;
    int l0  = (bx & 63) << 6;
    int tid = threadIdx.x;
    for (int i = tid; i < 64*DM; i += 256) {
        int t = i >> 6, c = i & 63;
        s_in[t][c] = in6[(b*LSEQ + l0 + t)*DM + c];
    }
    for (int i = tid; i < CIN_*DM; i += 256) {
        int o = i >> 6, c = i & 63;
        s_w[o][c] = w[i];
    }
    __syncthreads();
    int t  = tid & 63;
    int og = tid >> 6;
    for (int oi = 0; oi < 16; ++oi) {
        int o = og*16 + oi;
        float acc = bias[o];
        #pragma unroll 16
        for (int c = 0; c < DM; ++c) acc += s_w[o][c] * s_in[t][c];
        out[(b*CIN_ + o)*LSEQ + l0 + t] = acc;
    }
}

// ---------------- phase A: acc -> rmsnorm -> in_proj ----------------
// grid (NTOK/32, 2): blockIdx.y selects the 128-output half (y=0 -> xc_pre, y=1 -> z).
// Normalized x kept in K-major float4 layout for conflict-free LDS.128 reads.
__global__ __launch_bounds__(256) void k_block_a(const float* __restrict__ base,
                                                 const float* __restrict__ prev,
                                                 const float* __restrict__ norm_w,
                                                 const float* __restrict__ in_w) {
    __shared__ float  s_raw[32*68];
    __shared__ float4 s_x4 [16*33];    // [k4][token], pitch 33 -> conflict-free
    __shared__ float  s_xz [32*132];
    __shared__ float  s_rms[32];
    int tok0  = blockIdx.x * 32;
    int obase = blockIdx.y * 128;
    int tid   = threadIdx.x;

    for (int i = tid; i < 32*64; i += 256) {
        int t = i >> 6, c = i & 63;
        float v = base[(tok0 + t)*DM + c];
        if (prev) v += prev[(tok0 + t)*DM + c];
        s_raw[t*68 + c] = v;
    }
    __syncthreads();
    {   // rmsnorm: 8 threads per token, all 256 threads active -> full-warp shuffles
        int t = tid >> 3, j = tid & 7;
        float s = 0.f;
        #pragma unroll
        for (int k = 0; k < 8; ++k) { float v = s_raw[t*68 + j + 8*k]; s += v*v; }
        s += __shfl_xor_sync(~0u, s, 4, 8);
        s += __shfl_xor_sync(~0u, s, 2, 8);
        s += __shfl_xor_sync(~0u, s, 1, 8);
        if (j == 0) s_rms[t] = rsqrtf(s * (1.0f/64.0f) + 1e-5f);
    }
    __syncthreads();
    for (int i = tid; i < 32*64; i += 256) {
        int t = i >> 6, c = i & 63;
        float v = s_raw[t*68 + c] * s_rms[t] * norm_w[c];
        ((float*)s_x4)[(c >> 2)*132 + t*4 + (c & 3)] = v;
        if (blockIdx.y == 0) g_xn[(tok0 + t)*DM + c] = v;
    }
    __syncthreads();

    // in_proj GEMV: lane = token, warp wj covers 16 outputs of this CTA's half
    int lane = tid & 31, wj = tid >> 5;
    for (int g = 0; g < 4; ++g) {
        int ol = wj*16 + g*4;
        int o  = obase + ol;
        const float4* w0 = (const float4*)(in_w + (o+0)*64);
        const float4* w1 = (const float4*)(in_w + (o+1)*64);
        const float4* w2 = (const float4*)(in_w + (o+2)*64);
        const float4* w3 = (const float4*)(in_w + (o+3)*64);
        float a0 = 0.f, a1 = 0.f, a2 = 0.f, a3 = 0.f;
        #pragma unroll
        for (int k = 0; k < 16; ++k) {
            float4 xv = s_x4[k*33 + lane];
            float4 v0 = __ldg(&w0[k]), v1 = __ldg(&w1[k]);
            float4 v2 = __ldg(&w2[k]), v3 = __ldg(&w3[k]);
            a0 += v0.x*xv.x + v0.y*xv.y + v0.z*xv.z + v0.w*xv.w;
            a1 += v1.x*xv.x + v1.y*xv.y + v1.z*xv.z + v1.w*xv.w;
            a2 += v2.x*xv.x + v2.y*xv.y + v2.z*xv.z + v2.w*xv.w;
            a3 += v3.x*xv.x + v3.y*xv.y + v3.z*xv.z + v3.w*xv.w;
        }
        float* dst = s_xz + lane*132 + ol;
        dst[0] = a0; dst[1] = a1; dst[2] = a2; dst[3] = a3;
    }
    __syncthreads();
    // coalesced scatter to the right half
    float* gdst = blockIdx.y ? g_z : g_xcpre;
    for (int i = tid; i < 32*128; i += 256) {
        int t = i >> 7, ol = i & 127;
        gdst[(tok0 + t)*DI + ol] = s_xz[t*132 + ol];
    }
}

// ---------------- phase B: conv1d+SiLU, x_proj, dt_proj, SSM, gate, out_proj ----------------
// 16 tokens/CTA, 256 threads, grid 512. lane = (token<<1 | p); p splits outputs.
__global__ __launch_bounds__(256) void k_block_b(
        const float* __restrict__ cw,  const float* __restrict__ cb,
        const float* __restrict__ xp_w,
        const float* __restrict__ dt_w, const float* __restrict__ dt_b,
        const float* __restrict__ Dp,
        const float* __restrict__ out_w,
        const float* __restrict__ h_in, float* __restrict__ h_out,
        float* __restrict__ out_cur) {
    __shared__ float s_xc [16*132];
    __shared__ float s_ym [16*132];
    __shared__ float s_dl [16*129];
    __shared__ float s_dbc[16*65];
    __shared__ float s_A  [128*17];

    int tok0 = blockIdx.x * 16;
    int tid  = threadIdx.x;
    int l0   = tok0 & (LSEQ - 1);       // CTA within one batch (4096 % 16 == 0)

    for (int i = tid; i < DI*DS; i += 256) { int d = i >> 4, s = i & 15; s_A[d*17 + s] = g_A[i]; }

    // depthwise conv (taps l-1,l,l+1, zero pad at batch edges) + SiLU
    for (int i = tid; i < 16*DI; i += 256) {
        int t = i >> 7, d = i & 127;
        int l = l0 + t;
        int idx = (tok0 + t)*DI + d;
        float v = cb[d] + cw[d*3 + 1] * g_xcpre[idx];
        if (l > 0)        v += cw[d*3 + 0] * g_xcpre[idx - DI];
        if (l < LSEQ - 1) v += cw[d*3 + 2] * g_xcpre[idx + DI];
        v = v / (1.0f + __expf(-v));
        s_xc[t*132 + d] = v;
    }
    __syncthreads();

    int lane = tid & 31, wj = tid >> 5;
    int t16  = lane >> 1, p = lane & 1;

    // x_proj: 64 outputs; thread covers 4 outputs (o = p*32 + wj*4 + oi) for token t16
    {
        const float4* xrow = (const float4*)(s_xc + t16*132);
        int ob = p*32 + wj*4;
        const float4* w0 = (const float4*)(xp_w + (ob+0)*DI);
        const float4* w1 = (const float4*)(xp_w + (ob+1)*DI);
        const float4* w2 = (const float4*)(xp_w + (ob+2)*DI);
        const float4* w3 = (const float4*)(xp_w + (ob+3)*DI);
        float a0 = 0.f, a1 = 0.f, a2 = 0.f, a3 = 0.f;
        #pragma unroll
        for (int c = 0; c < 32; ++c) {
            float4 xv = xrow[c];
            float4 v0 = __ldg(&w0[c]), v1 = __ldg(&w1[c]);
            float4 v2 = __ldg(&w2[c]), v3 = __ldg(&w3[c]);
            a0 += v0.x*xv.x + v0.y*xv.y + v0.z*xv.z + v0.w*xv.w;
            a1 += v1.x*xv.x + v1.y*xv.y + v1.z*xv.z + v1.w*xv.w;
            a2 += v2.x*xv.x + v2.y*xv.y + v2.z*xv.z + v2.w*xv.w;
            a3 += v3.x*xv.x + v3.y*xv.y + v3.z*xv.z + v3.w*xv.w;
        }
        float* dst = s_dbc + t16*65 + ob;
        dst[0] = a0; dst[1] = a1; dst[2] = a2; dst[3] = a3;
    }
    __syncthreads();

    // dt_proj + softplus: thread covers 8 outputs (o = p*64 + wj*8 + oi) for token t16
    {
        float din[DR];
        #pragma unroll
        for (int r = 0; r < DR; ++r) din[r] = s_dbc[t16*65 + r];
        #pragma unroll
        for (int oi = 0; oi < 8; ++oi) {
            int o = p*64 + wj*8 + oi;
            const float4* wr = (const float4*)(dt_w + o*DR);
            float a = dt_b[o];
            #pragma unroll
            for (int r4 = 0; r4 < 8; ++r4) {
                float4 wv = __ldg(&wr[r4]);
                a += wv.x*din[4*r4] + wv.y*din[4*r4+1] + wv.z*din[4*r4+2] + wv.w*din[4*r4+3];
            }
            float sp = fmaxf(a, 0.f) + log1pf(__expf(-fabsf(a)));
            s_dl[t16*129 + o] = sp;
        }
    }
    __syncthreads();

    // SSM update + y + gating
    for (int i = tid; i < 16*DI; i += 256) {
        int t = i >> 7, d = i & 127;
        float dl  = s_dl[t*129 + d];
        float xcv = s_xc[t*132 + d];
        float dx  = dl * xcv;
        size_t hbase = ((size_t)(tok0 + t)*DI + d) * DS;
        float h[DS];
        if (h_in) {
            #pragma unroll
            for (int q = 0; q < 4; ++q) {
                float4 hv = *((const float4*)(h_in + hbase) + q);
                h[4*q] = hv.x; h[4*q+1] = hv.y; h[4*q+2] = hv.z; h[4*q+3] = hv.w;
            }
        } else {
            #pragma unroll
            for (int s = 0; s < DS; ++s) h[s] = 0.f;
        }
        float y = 0.f;
        #pragma unroll
        for (int s = 0; s < DS; ++s) {
            float dA = __expf(dl * s_A[d*17 + s]);
            float hn = dA * h[s] + dx * s_dbc[t*65 + 32 + s];
            h[s] = hn;
            y += hn * s_dbc[t*65 + 48 + s];
        }
        #pragma unroll
        for (int q = 0; q < 4; ++q)
            *((float4*)(h_out + hbase) + q) = make_float4(h[4*q], h[4*q+1], h[4*q+2], h[4*q+3]);
        y += __ldg(&Dp[d]) * xcv;
        float z  = g_z[(tok0 + t)*DI + d];
        float sz = z / (1.0f + __expf(-z));
        s_ym[t*132 + d] = y * sz;
    }
    __syncthreads();

    // out_proj: 64 outputs; thread covers 4 (o = p*32 + wj*4 + oi) for token t16
    {
        const float4* yrow = (const float4*)(s_ym + t16*132);
        int ob = p*32 + wj*4;
        const float4* w0 = (const float4*)(out_w + (ob+0)*DI);
        const float4* w1 = (const float4*)(out_w + (ob+1)*DI);
        const float4* w2 = (const float4*)(out_w + (ob+2)*DI);
        const float4* w3 = (const float4*)(out_w + (ob+3)*DI);
        float a0 = 0.f, a1 = 0.f, a2 = 0.f, a3 = 0.f;
        #pragma unroll
        for (int c = 0; c < 32; ++c) {
            float4 yv = yrow[c];
            float4 v0 = __ldg(&w0[c]), v1 = __ldg(&w1[c]);
            float4 v2 = __ldg(&w2[c]), v3 = __ldg(&w3[c]);
            a0 += v0.x*yv.x + v0.y*yv.y + v0.z*yv.z + v0.w*yv.w;
            a1 += v1.x*yv.x + v1.y*yv.y + v1.z*yv.z + v1.w*yv.w;
            a2 += v2.x*yv.x + v2.y*yv.y + v2.z*yv.z + v2.w*yv.w;
            a3 += v3.x*yv.x + v3.y*yv.y + v3.z*yv.z + v3.w*yv.w;
        }
        __syncthreads();   // s_dbc about to be reused
        float* dst = s_dbc + t16*65 + ob;
        dst[0] = a0; dst[1] = a1; dst[2] = a2; dst[3] = a3;
    }
    __syncthreads();
    for (int i = tid; i < 16*64; i += 256) {
        int t = i >> 6, o = i & 63;
        out_cur[(tok0 + t)*DM + o] = s_dbc[t*65 + o] + g_xn[(tok0 + t)*DM + o];
    }
}

// ---------------- host launch ----------------
extern "C" void kernel_launch(void* const* d_in, const int* in_sizes, int n_in,
                              void* d_out, int out_size) {
    const float* rgb    = (const float*)d_in[0];
    const float* dte    = (const float*)d_in[1];
    const float* c1w    = (const float*)d_in[2];
    const float* c1b    = (const float*)d_in[3];
    const float* c2w    = (const float*)d_in[4];
    const float* c2b    = (const float*)d_in[5];
    const float* c3w    = (const float*)d_in[6];
    const float* c3b    = (const float*)d_in[7];
    const float* normw  = (const float*)d_in[8];
    const float* inw    = (const float*)d_in[9];
    const float* convw  = (const float*)d_in[10];
    const float* convb  = (const float*)d_in[11];
    const float* xpw    = (const float*)d_in[12];
    const float* dtw    = (const float*)d_in[13];
    const float* dtb    = (const float*)d_in[14];
    const float* A_log  = (const float*)d_in[15];
    const float* Dpp    = (const float*)d_in[16];
    const float* outw   = (const float*)d_in[17];
    float* out = (float*)d_out;

    float *p_rgb, *p_dte, *p_O0, *p_O1, *p_h;
    cudaGetSymbolAddress((void**)&p_rgb, g_rgb);
    cudaGetSymbolAddress((void**)&p_dte, g_dte);
    cudaGetSymbolAddress((void**)&p_O0,  g_O0);
    cudaGetSymbolAddress((void**)&p_O1,  g_O1);
    cudaGetSymbolAddress((void**)&p_h,   g_h);

    const int conv_elems = BB*CIN_*LSEQ;                 // 524288
    const int h_elems    = NTOK*DI*DS;                   // 16777216
    float* h_final = (out_size >= conv_elems + h_elems) ? (out + conv_elems) : p_h;

    k_prep_A<<<(DI*DS + 255)/256, 256>>>(A_log);
    k_conv_in<<<BB*LSEQ/64, 256>>>(rgb, c1w, c1b, p_rgb);
    k_conv_in<<<BB*LSEQ/64, 256>>>(dte, c2w, c2b, p_dte);

    const float* bases[6] = { p_rgb, p_dte, p_rgb, p_dte, p_rgb, p_dte };
    float* outs[2] = { p_O0, p_O1 };
    const float* prev = nullptr;
    dim3 gridA(NTOK/32, 2);
    for (int k = 0; k < 6; ++k) {
        k_block_a<<<gridA, 256>>>(bases[k], prev, normw, inw);
        const float* h_in = (k == 0) ? nullptr : p_h;
        float* h_o        = (k == 5) ? h_final : p_h;
        k_block_b<<<NTOK/16, 256>>>(convw, convb, xpw, dtw, dtb, Dpp, outw,
                                    h_in, h_o, outs[k & 1]);
        prev = outs[k & 1];
    }
    k_conv3<<<BB*LSEQ/64, 256>>>(prev, c3w, c3b, out);
}

// round 7
// speedup vs baseline: 1.8118x; 1.4518x over previous
#include <cuda_runtime.h>
#include <math.h>

// Problem constants
#define BB      2
#define CIN_    64
#define LSEQ    4096            // H*W
#define NTOK    (BB*LSEQ)       // 8192
#define DM      64              // d_model
#define DI      128             // d_inner
#define DS      16              // d_state
#define DR      32              // dt_rank

// ---------------- device scratch (static, allocation-free) ----------------
__device__ float g_rgb  [NTOK*DM];
__device__ float g_dte  [NTOK*DM];
__device__ float g_xn   [NTOK*DM];
__device__ float g_xcpre[NTOK*DI];
__device__ float g_z    [NTOK*DI];
__device__ float g_O0   [NTOK*DM];
__device__ float g_O1   [NTOK*DM];
__device__ float g_h    [NTOK*DI*DS];   // 64 MB
__device__ float g_A    [DI*DS];

__device__ __forceinline__ float dot4(float4 a, float4 b) {
    return a.x*b.x + a.y*b.y + a.z*b.z + a.w*b.w;
}

// ---------------- A = -exp(A_log) ----------------
__global__ void k_prep_A(const float* __restrict__ A_log) {
    int i = blockIdx.x * blockDim.x + threadIdx.x;
    if (i < DI*DS) g_A[i] = -expf(A_log[i]);
}

// ---------------- 1x1 conv, channel-major in -> token-major out ----------------
// weight-stationary: thread owns output o, weight row in regs, x broadcast from smem
__global__ __launch_bounds__(256) void k_conv_in(const float* __restrict__ in,
                                                 const float* __restrict__ w,
                                                 const float* __restrict__ bias,
                                                 float* __restrict__ out) {
    __shared__ float s_in[64*68];          // [ll][c], pitch 68 (16B-aligned rows)
    int bx  = blockIdx.x;
    int b   = bx >> 6;
    int l0  = (bx & 63) << 6;
    int tid = threadIdx.x;
    for (int i = tid; i < CIN_*64; i += 256) {
        int c = i >> 6, ll = i & 63;
        s_in[ll*68 + c] = in[(b*CIN_ + c)*LSEQ + l0 + ll];
    }
    __syncthreads();
    int o  = tid & 63;
    int lg = tid >> 6;
    float4 wr[16];
    const float4* wrow = (const float4*)(w + o*CIN_);
    #pragma unroll
    for (int k = 0; k < 16; ++k) wr[k] = __ldg(&wrow[k]);
    float bo = __ldg(&bias[o]);
    for (int li = 0; li < 16; ++li) {
        int ll = lg*16 + li;
        const float4* xr = (const float4*)(s_in + ll*68);
        float a0 = 0.f, a1 = 0.f, a2 = 0.f, a3 = 0.f;
        #pragma unroll
        for (int k = 0; k < 4; ++k) {
            a0 += dot4(wr[k],    xr[k]);
            a1 += dot4(wr[k+4],  xr[k+4]);
            a2 += dot4(wr[k+8],  xr[k+8]);
            a3 += dot4(wr[k+12], xr[k+12]);
        }
        out[(b*LSEQ + l0 + ll)*DM + o] = bo + ((a0+a1)+(a2+a3));
    }
}

// ---------------- final 1x1 conv, token-major in -> channel-major out ----------------
__global__ __launch_bounds__(256) void k_conv3(const float* __restrict__ in6,
                                               const float* __restrict__ w,
                                               const float* __restrict__ bias,
                                               float* __restrict__ out) {
    __shared__ float s_in [64*68];         // [t][c]
    __shared__ float s_out[64*66];         // [t][o]
    int bx  = blockIdx.x;
    int b   = bx >> 6;
    int l0  = (bx & 63) << 6;
    int tid = threadIdx.x;
    for (int i = tid; i < 64*DM; i += 256) {
        int t = i >> 6, c = i & 63;
        s_in[t*68 + c] = in6[(b*LSEQ + l0 + t)*DM + c];
    }
    __syncthreads();
    int o  = tid & 63;
    int og = tid >> 6;
    float4 wr[16];
    const float4* wrow = (const float4*)(w + o*DM);
    #pragma unroll
    for (int k = 0; k < 16; ++k) wr[k] = __ldg(&wrow[k]);
    float bo = __ldg(&bias[o]);
    for (int ti = 0; ti < 16; ++ti) {
        int t = og*16 + ti;
        const float4* xr = (const float4*)(s_in + t*68);
        float a0 = 0.f, a1 = 0.f, a2 = 0.f, a3 = 0.f;
        #pragma unroll
        for (int k = 0; k < 4; ++k) {
            a0 += dot4(wr[k],    xr[k]);
            a1 += dot4(wr[k+4],  xr[k+4]);
            a2 += dot4(wr[k+8],  xr[k+8]);
            a3 += dot4(wr[k+12], xr[k+12]);
        }
        s_out[t*66 + o] = bo + ((a0+a1)+(a2+a3));
    }
    __syncthreads();
    for (int i = tid; i < 64*64; i += 256) {
        int oo = i >> 6, t = i & 63;
        out[(b*CIN_ + oo)*LSEQ + l0 + t] = s_out[t*66 + oo];
    }
}

// ---------------- phase A: acc -> rmsnorm -> in_proj (weight-stationary) ----------------
// 32 tokens/CTA, 256 threads, grid 256. Thread owns output o = tid (all 256 outputs),
// weight row (64 floats) in registers, x rows broadcast from smem, direct global store.
__global__ __launch_bounds__(256, 2) void k_block_a(const float* __restrict__ base,
                                                    const float* __restrict__ prev,
                                                    const float* __restrict__ norm_w,
                                                    const float* __restrict__ in_w) {
    __shared__ float s_x  [32*68];
    __shared__ float s_rms[32];
    int tok0 = blockIdx.x * 32;
    int tid  = threadIdx.x;

    for (int i = tid; i < 32*64; i += 256) {
        int t = i >> 6, c = i & 63;
        float v = base[(tok0 + t)*DM + c];
        if (prev) v += prev[(tok0 + t)*DM + c];
        s_x[t*68 + c] = v;
    }
    __syncthreads();
    {   // rmsnorm: 8 threads per token, all 256 threads -> full-warp shuffles
        int t = tid >> 3, j = tid & 7;
        float s = 0.f;
        #pragma unroll
        for (int k = 0; k < 8; ++k) { float v = s_x[t*68 + j + 8*k]; s += v*v; }
        s += __shfl_xor_sync(~0u, s, 4, 8);
        s += __shfl_xor_sync(~0u, s, 2, 8);
        s += __shfl_xor_sync(~0u, s, 1, 8);
        if (j == 0) s_rms[t] = rsqrtf(s * (1.0f/64.0f) + 1e-5f);
    }
    __syncthreads();
    for (int i = tid; i < 32*64; i += 256) {
        int t = i >> 6, c = i & 63;
        float v = s_x[t*68 + c] * s_rms[t] * norm_w[c];
        s_x[t*68 + c] = v;
        g_xn[(tok0 + t)*DM + c] = v;
    }
    __syncthreads();

    // weight row for output o = tid: 16 float4 = 64 regs, loaded once
    int o = tid;
    float4 wr[16];
    const float4* wrow = (const float4*)(in_w + o*64);
    #pragma unroll
    for (int k = 0; k < 16; ++k) wr[k] = __ldg(&wrow[k]);

    float* gdst = (o < DI) ? (g_xcpre + o) : (g_z + (o - DI));
    #pragma unroll 2
    for (int t = 0; t < 32; ++t) {
        const float4* xr = (const float4*)(s_x + t*68);
        float a0 = 0.f, a1 = 0.f, a2 = 0.f, a3 = 0.f;
        #pragma unroll
        for (int k = 0; k < 4; ++k) {
            a0 += dot4(wr[k],    xr[k]);
            a1 += dot4(wr[k+4],  xr[k+4]);
            a2 += dot4(wr[k+8],  xr[k+8]);
            a3 += dot4(wr[k+12], xr[k+12]);
        }
        gdst[(size_t)(tok0 + t)*DI] = (a0+a1)+(a2+a3);
    }
}

// ---------------- phase B: conv1d+SiLU, x_proj, dt_proj, SSM, gate, out_proj ----------------
// 32 tokens/CTA, 256 threads, grid 256. GEMVs weight-stationary with k-half partials.
// dynamic smem layout (floats):
#define SMB_XC    0                          // 32 x 132
#define SMB_YM    (SMB_XC   + 32*132)        // 32 x 132
#define SMB_DL    (SMB_YM   + 32*132)        // 32 x 129
#define SMB_DBC   (SMB_DL   + 32*129)        // 32 x 68 (float4-aligned rows)
#define SMB_A     (SMB_DBC  + 32*68)         // 128 x 17
#define SMB_PART  (SMB_A    + 128*17)        // 2 x 32 x 68
#define SMB_TOT   (SMB_PART + 2*32*68)

__global__ __launch_bounds__(256, 2) void k_block_b(
        const float* __restrict__ cw,  const float* __restrict__ cb,
        const float* __restrict__ xp_w,
        const float* __restrict__ dt_w, const float* __restrict__ dt_b,
        const float* __restrict__ Dp,
        const float* __restrict__ out_w,
        const float* __restrict__ h_in, float* __restrict__ h_out,
        float* __restrict__ out_cur) {
    extern __shared__ float sm[];
    float* s_xc   = sm + SMB_XC;
    float* s_ym   = sm + SMB_YM;
    float* s_dl   = sm + SMB_DL;
    float* s_dbc  = sm + SMB_DBC;
    float* s_A    = sm + SMB_A;
    float* s_part = sm + SMB_PART;

    int tok0 = blockIdx.x * 32;
    int tid  = threadIdx.x;
    int l0   = tok0 & (LSEQ - 1);       // CTA within one batch

    for (int i = tid; i < DI*DS; i += 256) { int d = i >> 4, s = i & 15; s_A[d*17 + s] = g_A[i]; }

    // depthwise conv (taps l-1,l,l+1, zero pad at batch edges) + SiLU
    for (int i = tid; i < 32*DI; i += 256) {
        int t = i >> 7, d = i & 127;
        int l = l0 + t;
        int idx = (tok0 + t)*DI + d;
        float v = cb[d] + cw[d*3 + 1] * g_xcpre[idx];
        if (l > 0)        v += cw[d*3 + 0] * g_xcpre[idx - DI];
        if (l < LSEQ - 1) v += cw[d*3 + 2] * g_xcpre[idx + DI];
        v = v / (1.0f + __expf(-v));
        s_xc[t*132 + d] = v;
    }
    __syncthreads();

    // ---- x_proj (64 out x 128 k), weight-stationary ----
    // thread: o = tid&63, kh = (tid>>6)&1 (k-half), th = tid>>7 (token-half)
    {
        int o  = tid & 63;
        int kh = (tid >> 6) & 1;
        int th = tid >> 7;
        float4 wr[16];
        const float4* wrow = (const float4*)(xp_w + o*DI) + kh*16;
        #pragma unroll
        for (int k = 0; k < 16; ++k) wr[k] = __ldg(&wrow[k]);
        float* pdst = s_part + kh*(32*68) + o;
        #pragma unroll 2
        for (int i = 0; i < 16; ++i) {
            int t = th*16 + i;
            const float4* xr = (const float4*)(s_xc + t*132) + kh*16;
            float a0 = 0.f, a1 = 0.f, a2 = 0.f, a3 = 0.f;
            #pragma unroll
            for (int k = 0; k < 4; ++k) {
                a0 += dot4(wr[k],    xr[k]);
                a1 += dot4(wr[k+4],  xr[k+4]);
                a2 += dot4(wr[k+8],  xr[k+8]);
                a3 += dot4(wr[k+12], xr[k+12]);
            }
            pdst[t*68] = (a0+a1)+(a2+a3);
        }
    }
    __syncthreads();
    // combine k-halves -> s_dbc
    for (int i = tid; i < 32*64; i += 256) {
        int t = i >> 6, o = i & 63;
        s_dbc[t*68 + o] = s_part[t*68 + o] + s_part[32*68 + t*68 + o];
    }
    __syncthreads();

    // ---- dt_proj + softplus (128 out x 32 k), weight-stationary ----
    // thread: o = tid&127, th = tid>>7; each handles 16 tokens, full k
    {
        int o  = tid & 127;
        int th = tid >> 7;
        float4 wr[8];
        const float4* wrow = (const float4*)(dt_w + o*DR);
        #pragma unroll
        for (int k = 0; k < 8; ++k) wr[k] = __ldg(&wrow[k]);
        float bo = __ldg(&dt_b[o]);
        #pragma unroll 2
        for (int i = 0; i < 16; ++i) {
            int t = th*16 + i;
            const float4* dr = (const float4*)(s_dbc + t*68);
            float a0 = 0.f, a1 = 0.f;
            #pragma unroll
            for (int k = 0; k < 4; ++k) {
                a0 += dot4(wr[k],   dr[k]);
                a1 += dot4(wr[k+4], dr[k+4]);
            }
            float a = bo + a0 + a1;
            float sp = fmaxf(a, 0.f) + log1pf(__expf(-fabsf(a)));
            s_dl[t*129 + o] = sp;
        }
    }
    __syncthreads();

    // ---- SSM update + y + gating ----
    for (int i = tid; i < 32*DI; i += 256) {
        int t = i >> 7, d = i & 127;
        float dl  = s_dl[t*129 + d];
        float xcv = s_xc[t*132 + d];
        float dx  = dl * xcv;
        size_t hbase = ((size_t)(tok0 + t)*DI + d) * DS;
        float h[DS];
        if (h_in) {
            #pragma unroll
            for (int q = 0; q < 4; ++q) {
                float4 hv = *((const float4*)(h_in + hbase) + q);
                h[4*q] = hv.x; h[4*q+1] = hv.y; h[4*q+2] = hv.z; h[4*q+3] = hv.w;
            }
        } else {
            #pragma unroll
            for (int s = 0; s < DS; ++s) h[s] = 0.f;
        }
        float y = 0.f;
        #pragma unroll
        for (int s = 0; s < DS; ++s) {
            float dA = __expf(dl * s_A[d*17 + s]);
            float hn = dA * h[s] + dx * s_dbc[t*68 + 32 + s];
            h[s] = hn;
            y += hn * s_dbc[t*68 + 48 + s];
        }
        #pragma unroll
        for (int q = 0; q < 4; ++q)
            *((float4*)(h_out + hbase) + q) = make_float4(h[4*q], h[4*q+1], h[4*q+2], h[4*q+3]);
        y += __ldg(&Dp[d]) * xcv;
        float z  = g_z[(tok0 + t)*DI + d];
        float sz = z / (1.0f + __expf(-z));
        s_ym[t*132 + d] = y * sz;
    }
    __syncthreads();

    // ---- out_proj (64 out x 128 k), weight-stationary, partials reuse s_part ----
    {
        int o  = tid & 63;
        int kh = (tid >> 6) & 1;
        int th = tid >> 7;
        float4 wr[16];
        const float4* wrow = (const float4*)(out_w + o*DI) + kh*16;
        #pragma unroll
        for (int k = 0; k < 16; ++k) wr[k] = __ldg(&wrow[k]);
        float* pdst = s_part + kh*(32*68) + o;
        #pragma unroll 2
        for (int i = 0; i < 16; ++i) {
            int t = th*16 + i;
            const float4* yr = (const float4*)(s_ym + t*132) + kh*16;
            float a0 = 0.f, a1 = 0.f, a2 = 0.f, a3 = 0.f;
            #pragma unroll
            for (int k = 0; k < 4; ++k) {
                a0 += dot4(wr[k],    yr[k]);
                a1 += dot4(wr[k+4],  yr[k+4]);
                a2 += dot4(wr[k+8],  yr[k+8]);
                a3 += dot4(wr[k+12], yr[k+12]);
            }
            pdst[t*68] = (a0+a1)+(a2+a3);
        }
    }
    __syncthreads();
    // combine + residual, coalesced store
    for (int i = tid; i < 32*64; i += 256) {
        int t = i >> 6, o = i & 63;
        float v = s_part[t*68 + o] + s_part[32*68 + t*68 + o];
        out_cur[(tok0 + t)*DM + o] = v + g_xn[(tok0 + t)*DM + o];
    }
}

// ---------------- host launch ----------------
extern "C" void kernel_launch(void* const* d_in, const int* in_sizes, int n_in,
                              void* d_out, int out_size) {
    const float* rgb    = (const float*)d_in[0];
    const float* dte    = (const float*)d_in[1];
    const float* c1w    = (const float*)d_in[2];
    const float* c1b    = (const float*)d_in[3];
    const float* c2w    = (const float*)d_in[4];
    const float* c2b    = (const float*)d_in[5];
    const float* c3w    = (const float*)d_in[6];
    const float* c3b    = (const float*)d_in[7];
    const float* normw  = (const float*)d_in[8];
    const float* inw    = (const float*)d_in[9];
    const float* convw  = (const float*)d_in[10];
    const float* convb  = (const float*)d_in[11];
    const float* xpw    = (const float*)d_in[12];
    const float* dtw    = (const float*)d_in[13];
    const float* dtb    = (const float*)d_in[14];
    const float* A_log  = (const float*)d_in[15];
    const float* Dpp    = (const float*)d_in[16];
    const float* outw   = (const float*)d_in[17];
    float* out = (float*)d_out;

    float *p_rgb, *p_dte, *p_O0, *p_O1, *p_h;
    cudaGetSymbolAddress((void**)&p_rgb, g_rgb);
    cudaGetSymbolAddress((void**)&p_dte, g_dte);
    cudaGetSymbolAddress((void**)&p_O0,  g_O0);
    cudaGetSymbolAddress((void**)&p_O1,  g_O1);
    cudaGetSymbolAddress((void**)&p_h,   g_h);

    const int smemB = SMB_TOT * (int)sizeof(float);
    cudaFuncSetAttribute(k_block_b, cudaFuncAttributeMaxDynamicSharedMemorySize, smemB);

    const int conv_elems = BB*CIN_*LSEQ;                 // 524288
    const int h_elems    = NTOK*DI*DS;                   // 16777216
    float* h_final = (out_size >= conv_elems + h_elems) ? (out + conv_elems) : p_h;

    k_prep_A<<<(DI*DS + 255)/256, 256>>>(A_log);
    k_conv_in<<<BB*LSEQ/64, 256>>>(rgb, c1w, c1b, p_rgb);
    k_conv_in<<<BB*LSEQ/64, 256>>>(dte, c2w, c2b, p_dte);

    const float* bases[6] = { p_rgb, p_dte, p_rgb, p_dte, p_rgb, p_dte };
    float* outs[2] = { p_O0, p_O1 };
    const float* prev = nullptr;
    for (int k = 0; k < 6; ++k) {
        k_block_a<<<NTOK/32, 256>>>(bases[k], prev, normw, inw);
        const float* h_in = (k == 0) ? nullptr : p_h;
        float* h_o        = (k == 5) ? h_final : p_h;
        k_block_b<<<NTOK/32, 256, smemB>>>(convw, convb, xpw, dtw, dtb, Dpp, outw,
                                           h_in, h_o, outs[k & 1]);
        prev = outs[k & 1];
    }
    k_conv3<<<BB*LSEQ/64, 256>>>(prev, c3w, c3b, out);
}